// round 4
// baseline (speedup 1.0000x reference)
#include <cuda_runtime.h>

#define NB      262144
#define NSLOTS  65536          // thread-slots, 4 elements each (2x f32x2)
#define BLOCK   64
#define GRID    (148 * 6)      // 888 blocks, 6 resident/SM, grid-stride
#define STRIDE  (GRID * BLOCK) // 56832

typedef unsigned long long u64;

__device__ __forceinline__ u64 pack2(float lo, float hi) {
    u64 r; asm("mov.b64 %0, {%1,%2};" : "=l"(r) : "f"(lo), "f"(hi)); return r;
}
__device__ __forceinline__ void unpack2(u64 v, float& lo, float& hi) {
    asm("mov.b64 {%0,%1}, %2;" : "=f"(lo), "=f"(hi) : "l"(v));
}
__device__ __forceinline__ u64 fma2(u64 a, u64 b, u64 c) {
    u64 r; asm("fma.rn.f32x2 %0, %1, %2, %3;" : "=l"(r) : "l"(a), "l"(b), "l"(c)); return r;
}
__device__ __forceinline__ u64 mul2(u64 a, u64 b) {
    u64 r; asm("mul.rn.f32x2 %0, %1, %2;" : "=l"(r) : "l"(a), "l"(b)); return r;
}
__device__ __forceinline__ u64 add2(u64 a, u64 b) {
    u64 r; asm("add.rn.f32x2 %0, %1, %2;" : "=l"(r) : "l"(a), "l"(b)); return r;
}
__device__ __forceinline__ u64 relu2(u64 x) {
    float lo, hi; unpack2(x, lo, hi);
    lo = fmaxf(lo, 0.0f); hi = fmaxf(hi, 0.0f);
    return pack2(lo, hi);
}

__global__ __launch_bounds__(BLOCK, 6)
void hybridq_kernel(const float* __restrict__ xq, const float* __restrict__ xc,
                    const float* __restrict__ qp,
                    const float* __restrict__ W1, const float* __restrict__ b1,
                    const float* __restrict__ W2, const float* __restrict__ b2,
                    const float* __restrict__ W3, const float* __restrict__ b3,
                    float* __restrict__ out)
{
    // Duplicated-f32x2 weights in SMEM. sW1 rows padded to 18 u64 for 16B align.
    __shared__ u64 sW1[32][18];
    __shared__ u64 sW2[32][16];   // W2 native [k][j] layout
    __shared__ u64 sW3[16];
    __shared__ u64 sb1[32];
    __shared__ u64 sb2[16];
    __shared__ float sxq[4][7 * BLOCK];   // staged xq rows, 4 element-groups

    const int tid = threadIdx.x;
    for (int i = tid; i < 32 * 17; i += BLOCK) {
        int k = i / 17, ii = i % 17;
        float w = W1[ii * 32 + k];
        sW1[k][ii] = pack2(w, w);
    }
    for (int i = tid; i < 32 * 16; i += BLOCK) {
        float w = W2[i];
        sW2[i / 16][i % 16] = pack2(w, w);
    }
    if (tid < 32) { float v = b1[tid]; sb1[tid] = pack2(v, v); }
    if (tid < 16) {
        float w = W3[tid]; sW3[tid] = pack2(w, w);
        float v = b2[tid]; sb2[tid] = pack2(v, v);
    }
    // qp into registers (same for all elements)
    float qpr1 = __ldg(qp + 1), qpr2 = __ldg(qp + 2), qpr3 = __ldg(qp + 3),
          qpr4 = __ldg(qp + 4), qpr5 = __ldg(qp + 5), qpr6 = __ldg(qp + 6);
    const float bb = __ldg(b3);
    __syncthreads();

    for (int bs = blockIdx.x * BLOCK; bs < NSLOTS; bs += STRIDE) {
        const int t  = bs + tid;
        const int e0 = t;
        const int e1 = t + NSLOTS;
        const int e2 = t + 2 * NSLOTS;
        const int e3 = t + 3 * NSLOTS;

        // ---- Stage xq rows for this block's 4 element groups (coalesced) ----
#pragma unroll
        for (int r = 0; r < 4; r++) {
            size_t base = 7ull * (size_t)(bs + r * NSLOTS);
#pragma unroll
            for (int j = 0; j < 7; j++)
                sxq[r][tid + j * BLOCK] = __ldg(xq + base + tid + j * BLOCK);
        }
        __syncthreads();

        // ---- Quantum feature: <Z0> = prod_{i=1..6} cos(x_q[i] + qp[i]) ----
        // (CNOT-ring GF(2): qubit-0 output = parity(b1..b6); factor per qubit
        //  = cos^2(h)-sin^2(h) = cos(2h) = cos(x+w); qubit 0's angle cancels.)
        float qf[4];
#pragma unroll
        for (int r = 0; r < 4; r++) {
            const float* row = &sxq[r][tid * 7];
            float v = __cosf(row[1] + qpr1);
            v *= __cosf(row[2] + qpr2);
            v *= __cosf(row[3] + qpr3);
            v *= __cosf(row[4] + qpr4);
            v *= __cosf(row[5] + qpr5);
            v *= __cosf(row[6] + qpr6);
            qf[r] = v;
        }
        __syncthreads();   // reads done; next iteration may overwrite sxq

        // ---- Inputs: feature 0 = q_out, features 1..16 = x_c ----
        u64 inA[17], inB[17];
        inA[0] = pack2(qf[0], qf[1]);
        inB[0] = pack2(qf[2], qf[3]);
        {
            const float4* c0 = (const float4*)(xc + (size_t)e0 * 16);
            const float4* c1 = (const float4*)(xc + (size_t)e1 * 16);
            const float4* c2 = (const float4*)(xc + (size_t)e2 * 16);
            const float4* c3 = (const float4*)(xc + (size_t)e3 * 16);
#pragma unroll
            for (int q = 0; q < 4; q++) {
                float4 a = __ldg(c0 + q);
                float4 b = __ldg(c1 + q);
                float4 c = __ldg(c2 + q);
                float4 d = __ldg(c3 + q);
                inA[1 + q * 4 + 0] = pack2(a.x, b.x);
                inA[1 + q * 4 + 1] = pack2(a.y, b.y);
                inA[1 + q * 4 + 2] = pack2(a.z, b.z);
                inA[1 + q * 4 + 3] = pack2(a.w, b.w);
                inB[1 + q * 4 + 0] = pack2(c.x, d.x);
                inB[1 + q * 4 + 1] = pack2(c.y, d.y);
                inB[1 + q * 4 + 2] = pack2(c.z, d.z);
                inB[1 + q * 4 + 3] = pack2(c.w, d.w);
            }
        }

        // ---- Fused layers 1+2 (split accumulator chains for ILP) ----
        u64 hA[16], hB[16];
#pragma unroll
        for (int j = 0; j < 16; j++) { hA[j] = sb2[j]; hB[j] = sb2[j]; }

#pragma unroll 4
        for (int k = 0; k < 32; k++) {
            const ulonglong2* r1 = (const ulonglong2*)&sW1[k][0];
            ulonglong2 w = r1[0];
            u64 bk = sb1[k];
            u64 aA0 = fma2(inA[0], w.x, bk);
            u64 aA1 = mul2(inA[1], w.y);
            u64 aB0 = fma2(inB[0], w.x, bk);
            u64 aB1 = mul2(inB[1], w.y);
#pragma unroll
            for (int i = 1; i < 8; i++) {
                w = r1[i];
                aA0 = fma2(inA[2 * i + 0], w.x, aA0);
                aA1 = fma2(inA[2 * i + 1], w.y, aA1);
                aB0 = fma2(inB[2 * i + 0], w.x, aB0);
                aB1 = fma2(inB[2 * i + 1], w.y, aB1);
            }
            u64 wl = sW1[k][16];
            aA0 = fma2(inA[16], wl, aA0);
            aB0 = fma2(inB[16], wl, aB0);
            u64 a = relu2(add2(aA0, aA1));
            u64 b = relu2(add2(aB0, aB1));
            const ulonglong2* r2 = (const ulonglong2*)&sW2[k][0];
#pragma unroll
            for (int j = 0; j < 8; j++) {
                ulonglong2 w2 = r2[j];
                hA[2 * j + 0] = fma2(a, w2.x, hA[2 * j + 0]);
                hA[2 * j + 1] = fma2(a, w2.y, hA[2 * j + 1]);
                hB[2 * j + 0] = fma2(b, w2.x, hB[2 * j + 0]);
                hB[2 * j + 1] = fma2(b, w2.y, hB[2 * j + 1]);
            }
        }

        // ---- Layer 3: 16 -> 1 ----
        u64 accA = pack2(bb, bb);
        u64 accB = accA;
#pragma unroll
        for (int j = 0; j < 16; j++) {
            accA = fma2(relu2(hA[j]), sW3[j], accA);
            accB = fma2(relu2(hB[j]), sW3[j], accB);
        }

        float o0, o1, o2, o3;
        unpack2(accA, o0, o1);
        unpack2(accB, o2, o3);
        out[e0] = o0;
        out[e1] = o1;
        out[e2] = o2;
        out[e3] = o3;
    }
}

extern "C" void kernel_launch(void* const* d_in, const int* in_sizes, int n_in,
                              void* d_out, int out_size)
{
    const float* xq = (const float*)d_in[0];
    const float* xc = (const float*)d_in[1];
    const float* qp = (const float*)d_in[2];
    const float* W1 = (const float*)d_in[3];
    const float* b1 = (const float*)d_in[4];
    const float* W2 = (const float*)d_in[5];
    const float* b2 = (const float*)d_in[6];
    const float* W3 = (const float*)d_in[7];
    const float* b3 = (const float*)d_in[8];
    float* out = (float*)d_out;

    hybridq_kernel<<<GRID, BLOCK>>>(xq, xc, qp, W1, b1, W2, b2, W3, b3, out);
}

// round 5
// speedup vs baseline: 1.4051x; 1.4051x over previous
#include <cuda_runtime.h>

#define NB 262144
#define NTHREADS (NB / 4)   // 4 elements per thread (2x f32x2 batch packs)
#define BLOCK 128

typedef unsigned long long u64;

__device__ __forceinline__ u64 pack2(float lo, float hi) {
    u64 r; asm("mov.b64 %0, {%1,%2};" : "=l"(r) : "f"(lo), "f"(hi)); return r;
}
__device__ __forceinline__ void unpack2(u64 v, float& lo, float& hi) {
    asm("mov.b64 {%0,%1}, %2;" : "=f"(lo), "=f"(hi) : "l"(v));
}
__device__ __forceinline__ u64 dup2(float w) {
    u64 r; asm("mov.b64 %0, {%1,%1};" : "=l"(r) : "f"(w)); return r;
}
__device__ __forceinline__ u64 fma2(u64 a, u64 b, u64 c) {
    u64 r; asm("fma.rn.f32x2 %0, %1, %2, %3;" : "=l"(r) : "l"(a), "l"(b), "l"(c)); return r;
}
__device__ __forceinline__ u64 mul2(u64 a, u64 b) {
    u64 r; asm("mul.rn.f32x2 %0, %1, %2;" : "=l"(r) : "l"(a), "l"(b)); return r;
}
__device__ __forceinline__ u64 add2(u64 a, u64 b) {
    u64 r; asm("add.rn.f32x2 %0, %1, %2;" : "=l"(r) : "l"(a), "l"(b)); return r;
}
__device__ __forceinline__ u64 relu2(u64 x) {
    float lo, hi; unpack2(x, lo, hi);
    lo = fmaxf(lo, 0.0f); hi = fmaxf(hi, 0.0f);
    return pack2(lo, hi);
}

__global__ __launch_bounds__(BLOCK, 3)
void hybridq_kernel(const float* __restrict__ xq, const float* __restrict__ xc,
                    const float* __restrict__ qp,
                    const float* __restrict__ W1, const float* __restrict__ b1,
                    const float* __restrict__ W2, const float* __restrict__ b2,
                    const float* __restrict__ W3, const float* __restrict__ b3,
                    float* __restrict__ out)
{
    // Big weights stored SCALAR (f32) — half the LDS return bytes of the
    // duplicated-u64 scheme; duplication into f32x2 happens in registers.
    // sW1 rows padded 17 -> 20 floats (80B) so float4 loads stay aligned.
    __shared__ float sW1[32][20];   // [out k][in i]
    __shared__ float sW2[32][16];   // W2 native [k][j]
    __shared__ u64 sW3[16];
    __shared__ u64 sb1[32];
    __shared__ u64 sb2[16];

    const int tid = threadIdx.x;
    for (int i = tid; i < 32 * 17; i += BLOCK) {
        int k = i / 17, ii = i % 17;
        sW1[k][ii] = W1[ii * 32 + k];
    }
    for (int i = tid; i < 32 * 16; i += BLOCK)
        sW2[i / 16][i % 16] = W2[i];
    if (tid < 32) { float v = b1[tid]; sb1[tid] = pack2(v, v); }
    if (tid < 16) {
        float w = W3[tid]; sW3[tid] = pack2(w, w);
        float v = b2[tid]; sb2[tid] = pack2(v, v);
    }
    __syncthreads();

    const int t  = blockIdx.x * BLOCK + tid;
    const int e0 = t;
    const int e1 = t + NTHREADS;
    const int e2 = t + 2 * NTHREADS;
    const int e3 = t + 3 * NTHREADS;

    // ---- Quantum feature: <Z0> = prod_{i=1..6} cos(x_q[i] + qp[i]) ----
    // (CNOT-ring GF(2): qubit-0 output = parity(b1..b6); per-qubit factor
    //  cos^2(h)-sin^2(h) = cos(2h) = cos(x+w); qubit 0's own angle cancels.)
    float q0 = 1.0f, q1 = 1.0f, q2 = 1.0f, q3 = 1.0f;
#pragma unroll
    for (int i = 1; i < 7; i++) {
        float w = __ldg(qp + i);
        q0 *= __cosf(__ldg(xq + e0 * 7 + i) + w);
        q1 *= __cosf(__ldg(xq + e1 * 7 + i) + w);
        q2 *= __cosf(__ldg(xq + e2 * 7 + i) + w);
        q3 *= __cosf(__ldg(xq + e3 * 7 + i) + w);
    }

    // ---- Inputs: feature 0 = q_out, features 1..16 = x_c ----
    u64 inA[17], inB[17];
    inA[0] = pack2(q0, q1);
    inB[0] = pack2(q2, q3);
    {
        const float4* c0 = (const float4*)(xc + (size_t)e0 * 16);
        const float4* c1 = (const float4*)(xc + (size_t)e1 * 16);
        const float4* c2 = (const float4*)(xc + (size_t)e2 * 16);
        const float4* c3 = (const float4*)(xc + (size_t)e3 * 16);
#pragma unroll
        for (int q = 0; q < 4; q++) {
            float4 a = __ldg(c0 + q);
            float4 b = __ldg(c1 + q);
            float4 c = __ldg(c2 + q);
            float4 d = __ldg(c3 + q);
            inA[1 + q * 4 + 0] = pack2(a.x, b.x);
            inA[1 + q * 4 + 1] = pack2(a.y, b.y);
            inA[1 + q * 4 + 2] = pack2(a.z, b.z);
            inA[1 + q * 4 + 3] = pack2(a.w, b.w);
            inB[1 + q * 4 + 0] = pack2(c.x, d.x);
            inB[1 + q * 4 + 1] = pack2(c.y, d.y);
            inB[1 + q * 4 + 2] = pack2(c.z, d.z);
            inB[1 + q * 4 + 3] = pack2(c.w, d.w);
        }
    }

    // ---- Fused layers 1+2: h2 += W2[k,:] * relu(W1[:,k].in + b1[k]) ----
    u64 hA[16], hB[16];
#pragma unroll
    for (int j = 0; j < 16; j++) { hA[j] = sb2[j]; hB[j] = sb2[j]; }

#pragma unroll 2
    for (int k = 0; k < 32; k++) {
        const float4* r1 = (const float4*)&sW1[k][0];
        float4 wq0 = r1[0];
        float4 wq1 = r1[1];
        float4 wq2 = r1[2];
        float4 wq3 = r1[3];
        float w16 = sW1[k][16];
        u64 bk = sb1[k];

        // Two independent accumulator chains per pack (even/odd inputs).
        u64 d;
        d = dup2(wq0.x);
        u64 aA0 = fma2(inA[0], d, bk);
        u64 aB0 = fma2(inB[0], d, bk);
        d = dup2(wq0.y);
        u64 aA1 = mul2(inA[1], d);
        u64 aB1 = mul2(inB[1], d);
        d = dup2(wq0.z); aA0 = fma2(inA[2], d, aA0);  aB0 = fma2(inB[2], d, aB0);
        d = dup2(wq0.w); aA1 = fma2(inA[3], d, aA1);  aB1 = fma2(inB[3], d, aB1);
        d = dup2(wq1.x); aA0 = fma2(inA[4], d, aA0);  aB0 = fma2(inB[4], d, aB0);
        d = dup2(wq1.y); aA1 = fma2(inA[5], d, aA1);  aB1 = fma2(inB[5], d, aB1);
        d = dup2(wq1.z); aA0 = fma2(inA[6], d, aA0);  aB0 = fma2(inB[6], d, aB0);
        d = dup2(wq1.w); aA1 = fma2(inA[7], d, aA1);  aB1 = fma2(inB[7], d, aB1);
        d = dup2(wq2.x); aA0 = fma2(inA[8], d, aA0);  aB0 = fma2(inB[8], d, aB0);
        d = dup2(wq2.y); aA1 = fma2(inA[9], d, aA1);  aB1 = fma2(inB[9], d, aB1);
        d = dup2(wq2.z); aA0 = fma2(inA[10], d, aA0); aB0 = fma2(inB[10], d, aB0);
        d = dup2(wq2.w); aA1 = fma2(inA[11], d, aA1); aB1 = fma2(inB[11], d, aB1);
        d = dup2(wq3.x); aA0 = fma2(inA[12], d, aA0); aB0 = fma2(inB[12], d, aB0);
        d = dup2(wq3.y); aA1 = fma2(inA[13], d, aA1); aB1 = fma2(inB[13], d, aB1);
        d = dup2(wq3.z); aA0 = fma2(inA[14], d, aA0); aB0 = fma2(inB[14], d, aB0);
        d = dup2(wq3.w); aA1 = fma2(inA[15], d, aA1); aB1 = fma2(inB[15], d, aB1);
        d = dup2(w16);   aA0 = fma2(inA[16], d, aA0); aB0 = fma2(inB[16], d, aB0);

        u64 a = relu2(add2(aA0, aA1));
        u64 b = relu2(add2(aB0, aB1));

        const float4* r2 = (const float4*)&sW2[k][0];
#pragma unroll
        for (int jq = 0; jq < 4; jq++) {
            float4 w2 = r2[jq];
            u64 d0 = dup2(w2.x);
            u64 d1 = dup2(w2.y);
            u64 d2 = dup2(w2.z);
            u64 d3 = dup2(w2.w);
            hA[4 * jq + 0] = fma2(a, d0, hA[4 * jq + 0]);
            hA[4 * jq + 1] = fma2(a, d1, hA[4 * jq + 1]);
            hA[4 * jq + 2] = fma2(a, d2, hA[4 * jq + 2]);
            hA[4 * jq + 3] = fma2(a, d3, hA[4 * jq + 3]);
            hB[4 * jq + 0] = fma2(b, d0, hB[4 * jq + 0]);
            hB[4 * jq + 1] = fma2(b, d1, hB[4 * jq + 1]);
            hB[4 * jq + 2] = fma2(b, d2, hB[4 * jq + 2]);
            hB[4 * jq + 3] = fma2(b, d3, hB[4 * jq + 3]);
        }
    }

    // ---- Layer 3: 16 -> 1 ----
    float bb = __ldg(b3);
    u64 accA = pack2(bb, bb);
    u64 accB = accA;
#pragma unroll
    for (int j = 0; j < 16; j++) {
        accA = fma2(relu2(hA[j]), sW3[j], accA);
        accB = fma2(relu2(hB[j]), sW3[j], accB);
    }

    float o0, o1, o2, o3;
    unpack2(accA, o0, o1);
    unpack2(accB, o2, o3);
    out[e0] = o0;
    out[e1] = o1;
    out[e2] = o2;
    out[e3] = o3;
}

extern "C" void kernel_launch(void* const* d_in, const int* in_sizes, int n_in,
                              void* d_out, int out_size)
{
    const float* xq = (const float*)d_in[0];
    const float* xc = (const float*)d_in[1];
    const float* qp = (const float*)d_in[2];
    const float* W1 = (const float*)d_in[3];
    const float* b1 = (const float*)d_in[4];
    const float* W2 = (const float*)d_in[5];
    const float* b2 = (const float*)d_in[6];
    const float* W3 = (const float*)d_in[7];
    const float* b3 = (const float*)d_in[8];
    float* out = (float*)d_out;

    hybridq_kernel<<<NTHREADS / BLOCK, BLOCK>>>(xq, xc, qp, W1, b1, W2, b2, W3, b3, out);
}

// round 6
// speedup vs baseline: 1.5122x; 1.0762x over previous
#include <cuda_runtime.h>

#define NB 262144
#define NTHREADS (NB / 4)   // 4 elements per thread
#define BLOCK 128

typedef unsigned long long u64;

__device__ __forceinline__ u64 pack2(float lo, float hi) {
    u64 r; asm("mov.b64 %0, {%1,%2};" : "=l"(r) : "f"(lo), "f"(hi)); return r;
}
__device__ __forceinline__ void unpack2(u64 v, float& lo, float& hi) {
    asm("mov.b64 {%0,%1}, %2;" : "=f"(lo), "=f"(hi) : "l"(v));
}
__device__ __forceinline__ u64 fma2(u64 a, u64 b, u64 c) {
    u64 r; asm("fma.rn.f32x2 %0, %1, %2, %3;" : "=l"(r) : "l"(a), "l"(b), "l"(c)); return r;
}
__device__ __forceinline__ u64 mul2(u64 a, u64 b) {
    u64 r; asm("mul.rn.f32x2 %0, %1, %2;" : "=l"(r) : "l"(a), "l"(b)); return r;
}
__device__ __forceinline__ u64 relu2(u64 x) {
    float lo, hi; unpack2(x, lo, hi);
    lo = fmaxf(lo, 0.0f); hi = fmaxf(hi, 0.0f);
    return pack2(lo, hi);
}

__global__ __launch_bounds__(BLOCK, 3)
void hybridq_kernel(const float* __restrict__ xq, const float* __restrict__ xc,
                    const float* __restrict__ qp,
                    const float* __restrict__ W1, const float* __restrict__ b1,
                    const float* __restrict__ W2, const float* __restrict__ b2,
                    const float* __restrict__ W3, const float* __restrict__ b3,
                    float* __restrict__ out)
{
    // Feature-pair-packed weights: each u64 holds TWO DISTINCT weights
    // (no duplication, no dup-MOVs at use time).
    // Feature order: [xc0..xc15] as 8 pairs, q as scalar 17th feature.
    __shared__ u64 sW1[32][8];   // [k][pair j] = (W1[1+2j][k], W1[2+2j][k])
    __shared__ u64 sWqb[32];     // (W1[0][k], b1[k])
    __shared__ u64 sW2[32 * 8];  // W2 native row-major viewed as u64 pairs
    __shared__ u64 sW3[8];       // W3 native pairs
    __shared__ u64 sb2[8];       // b2 native pairs

    const int tid = threadIdx.x;
    for (int i = tid; i < 32 * 8; i += BLOCK) {
        int k = i / 8, j = i % 8;
        sW1[k][j] = pack2(W1[(1 + 2 * j) * 32 + k], W1[(2 + 2 * j) * 32 + k]);
    }
    for (int i = tid; i < 32 * 8; i += BLOCK)
        sW2[i] = ((const u64*)W2)[i];
    if (tid < 32) sWqb[tid] = pack2(W1[tid], b1[tid]);   // W1[0*32+k], b1[k]
    if (tid < 8) {
        sW3[tid] = ((const u64*)W3)[tid];
        sb2[tid] = ((const u64*)b2)[tid];
    }
    __syncthreads();

    const int t  = blockIdx.x * BLOCK + tid;
    const int e0 = t;
    const int e1 = t + NTHREADS;
    const int e2 = t + 2 * NTHREADS;
    const int e3 = t + 3 * NTHREADS;

    // ---- Quantum feature: <Z0> = prod_{i=1..6} cos(x_q[i] + qp[i]) ----
    // (CNOT-ring GF(2): qubit-0 output = parity(b1..b6); per-qubit factor
    //  cos^2(h)-sin^2(h) = cos(2h) = cos(x+w); qubit 0's own angle cancels.)
    float q[4] = {1.0f, 1.0f, 1.0f, 1.0f};
#pragma unroll
    for (int i = 1; i < 7; i++) {
        float w = __ldg(qp + i);
        q[0] *= __cosf(__ldg(xq + e0 * 7 + i) + w);
        q[1] *= __cosf(__ldg(xq + e1 * 7 + i) + w);
        q[2] *= __cosf(__ldg(xq + e2 * 7 + i) + w);
        q[3] *= __cosf(__ldg(xq + e3 * 7 + i) + w);
    }

    // ---- xc features: native f32x2 pairs, straight from LDG.128 ----
    u64 in[4][8];
    {
        const ulonglong2* c0 = (const ulonglong2*)(xc + (size_t)e0 * 16);
        const ulonglong2* c1 = (const ulonglong2*)(xc + (size_t)e1 * 16);
        const ulonglong2* c2 = (const ulonglong2*)(xc + (size_t)e2 * 16);
        const ulonglong2* c3 = (const ulonglong2*)(xc + (size_t)e3 * 16);
#pragma unroll
        for (int p = 0; p < 4; p++) {
            ulonglong2 a = c0[p]; in[0][2 * p] = a.x; in[0][2 * p + 1] = a.y;
            ulonglong2 b = c1[p]; in[1][2 * p] = b.x; in[1][2 * p + 1] = b.y;
            ulonglong2 c = c2[p]; in[2][2 * p] = c.x; in[2][2 * p + 1] = c.y;
            ulonglong2 d = c3[p]; in[3][2 * p] = d.x; in[3][2 * p + 1] = d.y;
        }
    }

    // ---- h2 accumulators: 8 output-pairs per element, init with b2 ----
    u64 h2[4][8];
#pragma unroll
    for (int e = 0; e < 4; e++)
#pragma unroll
        for (int j = 0; j < 8; j++)
            h2[e][j] = sb2[j];

    // ---- Fused layers 1+2 ----
#pragma unroll 2
    for (int k = 0; k < 32; k++) {
        const ulonglong2* r1 = (const ulonglong2*)&sW1[k][0];
        ulonglong2 w01 = r1[0];
        ulonglong2 w23 = r1[1];
        ulonglong2 w45 = r1[2];
        ulonglong2 w67 = r1[3];
        float wq, b1k;
        unpack2(sWqb[k], wq, b1k);

        u64 a2[4];
#pragma unroll
        for (int e = 0; e < 4; e++) {
            u64 acc = mul2(in[e][0], w01.x);
            acc = fma2(in[e][1], w01.y, acc);
            acc = fma2(in[e][2], w23.x, acc);
            acc = fma2(in[e][3], w23.y, acc);
            acc = fma2(in[e][4], w45.x, acc);
            acc = fma2(in[e][5], w45.y, acc);
            acc = fma2(in[e][6], w67.x, acc);
            acc = fma2(in[e][7], w67.y, acc);
            float lo, hi;
            unpack2(acc, lo, hi);                 // free: register pair
            float s = fmaf(q[e], wq, b1k) + lo + hi;
            s = fmaxf(s, 0.0f);
            a2[e] = pack2(s, s);                  // only dup left
        }

        const ulonglong2* r2 = (const ulonglong2*)&sW2[k * 8];
        ulonglong2 v01 = r2[0];
        ulonglong2 v23 = r2[1];
        ulonglong2 v45 = r2[2];
        ulonglong2 v67 = r2[3];
#pragma unroll
        for (int e = 0; e < 4; e++) {
            h2[e][0] = fma2(a2[e], v01.x, h2[e][0]);
            h2[e][1] = fma2(a2[e], v01.y, h2[e][1]);
            h2[e][2] = fma2(a2[e], v23.x, h2[e][2]);
            h2[e][3] = fma2(a2[e], v23.y, h2[e][3]);
            h2[e][4] = fma2(a2[e], v45.x, h2[e][4]);
            h2[e][5] = fma2(a2[e], v45.y, h2[e][5]);
            h2[e][6] = fma2(a2[e], v67.x, h2[e][6]);
            h2[e][7] = fma2(a2[e], v67.y, h2[e][7]);
        }
    }

    // ---- Layer 3: relu(h2) . W3 + b3, pairwise then hsum ----
    float bb = __ldg(b3);
    float o[4];
#pragma unroll
    for (int e = 0; e < 4; e++) {
        u64 acc = mul2(relu2(h2[e][0]), sW3[0]);
#pragma unroll
        for (int j = 1; j < 8; j++)
            acc = fma2(relu2(h2[e][j]), sW3[j], acc);
        float lo, hi;
        unpack2(acc, lo, hi);
        o[e] = bb + lo + hi;
    }

    out[e0] = o[0];
    out[e1] = o[1];
    out[e2] = o[2];
    out[e3] = o[3];
}

extern "C" void kernel_launch(void* const* d_in, const int* in_sizes, int n_in,
                              void* d_out, int out_size)
{
    const float* xq = (const float*)d_in[0];
    const float* xc = (const float*)d_in[1];
    const float* qp = (const float*)d_in[2];
    const float* W1 = (const float*)d_in[3];
    const float* b1 = (const float*)d_in[4];
    const float* W2 = (const float*)d_in[5];
    const float* b2 = (const float*)d_in[6];
    const float* W3 = (const float*)d_in[7];
    const float* b3 = (const float*)d_in[8];
    float* out = (float*)d_out;

    hybridq_kernel<<<NTHREADS / BLOCK, BLOCK>>>(xq, xc, qp, W1, b1, W2, b2, W3, b3, out);
}